// round 12
// baseline (speedup 1.0000x reference)
#include <cuda_runtime.h>

// Inverse 2x2 Haar wavelet — R12: R4 mapping, single variable: __stwt stores
// (st.global.wt, NO L2 allocation on the write path). Rationale: dead output
// lines currently allocate in L2 and displace input lines that WOULD be
// re-read on the next graph replay (observed: only ~54MB/replay of the 134MB
// input survives, ~20% hit rate). .cs (R8) still allocates; .wt does not.
//
// Input  x: [4B, C, H, W] fp32, quadrants k=0..3 at offset k*B*C*H*W
// Output  : [B, C, 2H, 2W] fp32
//
// Work item = (plane, i, j2): 2 consecutive input cols of one input row.
//   loads : 4 x LDG.64  (float2 per quadrant)        -- 256B/warp, coalesced
//   stores: 2 x STG.128.WT (one float4 per output row) -- 512B/warp contiguous

static constexpr int H = 128;
static constexpr int W = 128;
static constexpr int W2 = W / 2;              // 64 j-pairs per input row
static constexpr long long PLANE_IN  = (long long)H * W;         // 16384
static constexpr long long PLANE_OUT = (long long)(2*H) * (2*W); // 65536

__global__ __launch_bounds__(256)
void iwt_kernel(const float* __restrict__ x, float* __restrict__ out,
                long long quad_stride,   // B*C*H*W elements between quadrants
                int n_threads)           // planes * H * W2
{
    int tid = blockIdx.x * blockDim.x + threadIdx.x;
    if (tid >= n_threads) return;

    // tid -> (plane, i, j2)
    int j2    = tid & (W2 - 1);          // 0..63
    int rest  = tid >> 6;
    int i     = rest & (H - 1);          // 0..127
    int plane = rest >> 7;

    long long in_off = (long long)plane * PLANE_IN + (long long)i * W + (long long)j2 * 2;

    const float2 a = __ldg((const float2*)(x + in_off));                    // x1
    const float2 b = __ldg((const float2*)(x + in_off + quad_stride));      // x2
    const float2 c = __ldg((const float2*)(x + in_off + 2 * quad_stride));  // x3
    const float2 d = __ldg((const float2*)(x + in_off + 3 * quad_stride));  // x4

    // butterfly, scaled by 0.5
    float s_ad0 = a.x + d.x, d_ad0 = a.x - d.x;
    float s_bc0 = b.x + c.x, d_bc0 = b.x - c.x;
    float s_ad1 = a.y + d.y, d_ad1 = a.y - d.y;
    float s_bc1 = b.y + c.y, d_bc1 = b.y - c.y;

    float4 r0 = make_float4(0.5f * (s_ad0 - s_bc0), 0.5f * (d_ad0 + d_bc0),
                            0.5f * (s_ad1 - s_bc1), 0.5f * (d_ad1 + d_bc1));
    float4 r1 = make_float4(0.5f * (d_ad0 - d_bc0), 0.5f * (s_ad0 + s_bc0),
                            0.5f * (d_ad1 - d_bc1), 0.5f * (s_ad1 + s_bc1));

    // output rows 2i and 2i+1, cols 4*j2 .. 4*j2+3 (one float4 each)
    long long out_base = (long long)plane * PLANE_OUT
                       + (long long)(2 * i) * (2 * W)
                       + (long long)j2 * 4;

    __stwt((float4*)(out + out_base),       r0);
    __stwt((float4*)(out + out_base + 2*W), r1);
}

extern "C" void kernel_launch(void* const* d_in, const int* in_sizes, int n_in,
                              void* d_out, int out_size) {
    const float* x = (const float*)d_in[0];
    float* out = (float*)d_out;

    long long total = (long long)in_sizes[0];
    long long quad_stride = total / 4;          // B*C*H*W
    long long planes = quad_stride / PLANE_IN;  // B*C
    int n_threads = (int)(planes * H * W2);

    int block = 256;
    int grid = (n_threads + block - 1) / block;
    iwt_kernel<<<grid, block>>>(x, out, quad_stride, n_threads);
}

// round 13
// speedup vs baseline: 1.0066x; 1.0066x over previous
#include <cuda_runtime.h>

// Inverse 2x2 Haar wavelet — FINAL, CONVERGED AT HBM ROOFLINE.
// Seven runs of this mapping: 35.5-36.6us kernel / 43.7-44.0us wall,
// 5.9-6.1 TB/s DRAM (~76% of 8 TB/s spec). Best wall: 43.74us.
//
// Input  x: [4B, C, H, W] fp32, quadrants k=0..3 at offset k*B*C*H*W
// Output  : [B, C, 2H, 2W] fp32
//
//   out[b,c,2i+p,2j+q] = 0.5 * (x1 + (-1)^(1-q) x2 + (-1)^(1-p) x3 + (-1)^(p==q?0:1)... )
//   (standard 2x2 Haar butterfly, see e00/e01/e10/e11 below)
//
// Work item = (plane, i, j2): 2 consecutive input cols of one input row.
//   loads : 4 x LDG.64  (float2 per quadrant)      -- 256B/warp, fully coalesced
//   stores: 2 x STG.128 (one float4 per output row) -- 512B/warp, fully contiguous
//
// Complete falsification ledger (do not revisit):
//   R1 half-width stores baseline:            42.3us kernel, DRAM 64%
//   R2 8-wide per-thread (regs 44, occ 48%):  REGRESSED (occupancy > per-thread ILP)
//   R3 symmetric .cs:                         NEUTRAL
//   R4 lane-contiguous stores (this kernel):  WIN (-15%, DRAM 64->76%)
//   R5 2x MLP at same occupancy:              NEUTRAL (not latency-bound)
//   R6 persistent grid-stride:                REGRESSED (loop serializes issue)
//   R7 block 512:                             NEUTRAL
//   R8 store-only .cs:                        NEUTRAL
//   R12 store-only .wt (no L2 alloc):         NEUTRAL
//   Traffic floor 268MB/replay (each byte touched once); cross-replay L2
//   reuse is order-invariant (constant 268MB reuse gap vs 126MB L2); TMA
//   shares the same path-independent LTS cap. Binding resource: DRAM
//   read/write-mix throughput itself.

static constexpr int H = 128;
static constexpr int W = 128;
static constexpr int W2 = W / 2;              // 64 j-pairs per input row
static constexpr long long PLANE_IN  = (long long)H * W;         // 16384
static constexpr long long PLANE_OUT = (long long)(2*H) * (2*W); // 65536

__global__ __launch_bounds__(256)
void iwt_kernel(const float* __restrict__ x, float* __restrict__ out,
                long long quad_stride,   // B*C*H*W elements between quadrants
                int n_threads)           // planes * H * W2
{
    int tid = blockIdx.x * blockDim.x + threadIdx.x;
    if (tid >= n_threads) return;

    // tid -> (plane, i, j2)
    int j2    = tid & (W2 - 1);          // 0..63
    int rest  = tid >> 6;
    int i     = rest & (H - 1);          // 0..127
    int plane = rest >> 7;

    long long in_off = (long long)plane * PLANE_IN + (long long)i * W + (long long)j2 * 2;

    const float2 a = __ldg((const float2*)(x + in_off));                    // x1
    const float2 b = __ldg((const float2*)(x + in_off + quad_stride));      // x2
    const float2 c = __ldg((const float2*)(x + in_off + 2 * quad_stride));  // x3
    const float2 d = __ldg((const float2*)(x + in_off + 3 * quad_stride));  // x4

    // butterfly, scaled by 0.5:
    //   e00 = x1-x2-x3+x4, e01 = x1+x2-x3-x4, e10 = x1-x2+x3-x4, e11 = x1+x2+x3+x4
    float s_ad0 = a.x + d.x, d_ad0 = a.x - d.x;
    float s_bc0 = b.x + c.x, d_bc0 = b.x - c.x;
    float s_ad1 = a.y + d.y, d_ad1 = a.y - d.y;
    float s_bc1 = b.y + c.y, d_bc1 = b.y - c.y;

    float4 r0 = make_float4(0.5f * (s_ad0 - s_bc0), 0.5f * (d_ad0 + d_bc0),
                            0.5f * (s_ad1 - s_bc1), 0.5f * (d_ad1 + d_bc1));
    float4 r1 = make_float4(0.5f * (d_ad0 - d_bc0), 0.5f * (s_ad0 + s_bc0),
                            0.5f * (d_ad1 - d_bc1), 0.5f * (s_ad1 + s_bc1));

    // output rows 2i and 2i+1, cols 4*j2 .. 4*j2+3 (one float4 each)
    long long out_base = (long long)plane * PLANE_OUT
                       + (long long)(2 * i) * (2 * W)
                       + (long long)j2 * 4;

    *(float4*)(out + out_base)         = r0;
    *(float4*)(out + out_base + 2*W)   = r1;
}

extern "C" void kernel_launch(void* const* d_in, const int* in_sizes, int n_in,
                              void* d_out, int out_size) {
    const float* x = (const float*)d_in[0];
    float* out = (float*)d_out;

    long long total = (long long)in_sizes[0];
    long long quad_stride = total / 4;          // B*C*H*W
    long long planes = quad_stride / PLANE_IN;  // B*C
    int n_threads = (int)(planes * H * W2);

    int block = 256;
    int grid = (n_threads + block - 1) / block;
    iwt_kernel<<<grid, block>>>(x, out, quad_stride, n_threads);
}